// round 14
// baseline (speedup 1.0000x reference)
#include <cuda_runtime.h>
#include <cuda_fp16.h>
#include <math.h>
#include <stdint.h>

#define CDIM  768
#define TDIM  1024
#define BDIM  8
#define MROWS 8192
#define FDIM  3072
#define NHEAD 12
#define HSIZE 64
#define QKVW  2304
#define NPERSIST 296     // 148 SMs x 2 CTAs

// ===========================================================================
// Scratch (no cudaMalloc allowed)
// ===========================================================================
__device__ __half g_h   [MROWS * CDIM];
__device__ __half g_qkv [MROWS * QKVW];
__device__ __half g_att [MROWS * CDIM];
__device__ __half g_h2  [MROWS * CDIM];
__device__ __half g_ff  [MROWS * FDIM];
__device__ float  g_x2  [MROWS * CDIM];
__device__ __half g_Wqkv[QKVW * CDIM];
__device__ __half g_Wo  [CDIM * CDIM];
__device__ __half g_W1  [CDIM * FDIM];
__device__ __half g_W2  [FDIM * CDIM];

__device__ __forceinline__ uint32_t smem_u32(const void* p) {
    uint32_t a;
    asm("{ .reg .u64 t; cvta.to.shared.u64 t, %1; cvt.u32.u64 %0, t; }"
        : "=r"(a) : "l"(p));
    return a;
}
#define SWZ(off) ((off) ^ (((off) >> 3) & 0x70))

__device__ __forceinline__ void ldsm4(uint32_t* r, uint32_t addr) {
    asm volatile("ldmatrix.sync.aligned.m8n8.x4.shared.b16 {%0,%1,%2,%3}, [%4];"
                 : "=r"(r[0]), "=r"(r[1]), "=r"(r[2]), "=r"(r[3]) : "r"(addr));
}
__device__ __forceinline__ void ldsm4t(uint32_t* r, uint32_t addr) {
    asm volatile("ldmatrix.sync.aligned.m8n8.x4.trans.shared.b16 {%0,%1,%2,%3}, [%4];"
                 : "=r"(r[0]), "=r"(r[1]), "=r"(r[2]), "=r"(r[3]) : "r"(addr));
}
__device__ __forceinline__ void mma16816(float* d, const uint32_t* a,
                                         uint32_t b0, uint32_t b1) {
    asm volatile("mma.sync.aligned.m16n8k16.row.col.f32.f16.f16.f32 "
                 "{%0,%1,%2,%3}, {%4,%5,%6,%7}, {%8,%9}, {%0,%1,%2,%3};"
                 : "+f"(d[0]), "+f"(d[1]), "+f"(d[2]), "+f"(d[3])
                 : "r"(a[0]), "r"(a[1]), "r"(a[2]), "r"(a[3]), "r"(b0), "r"(b1));
}
__device__ __forceinline__ uint32_t pack_h2(float a, float b) {
    __half2 h = __floats2half2_rn(a, b);
    return *(uint32_t*)&h;
}
#define CP_ASYNC16(dst, src) \
    asm volatile("cp.async.cg.shared.global [%0], [%1], 16;" :: "r"(dst), "l"(src))
#define CP_COMMIT() asm volatile("cp.async.commit_group;" ::: "memory")
#define CP_WAIT(n)  asm volatile("cp.async.wait_group %0;" :: "n"(n) : "memory")

// ===========================================================================
// Weight transpose:  W[K,N] fp32 -> Wt[N,K] fp16.  64x64 tiles, 256 thr.
// ===========================================================================
__device__ __forceinline__ void wtrans_body(const float* __restrict__ W,
                                            __half* __restrict__ Wt,
                                            int K, int N)
{
    __shared__ float t[64][65];
    const int n0 = blockIdx.x * 64, k0 = blockIdx.y * 64;
    const int tid = threadIdx.x;
    #pragma unroll
    for (int i = 0; i < 4; i++) {
        const int idx = tid + i * 256;
        const int kr = idx >> 4, nc = (idx & 15) * 4;
        const float4 v = *(const float4*)(W + (size_t)(k0 + kr) * N + n0 + nc);
        t[kr][nc] = v.x; t[kr][nc + 1] = v.y; t[kr][nc + 2] = v.z; t[kr][nc + 3] = v.w;
    }
    __syncthreads();
    #pragma unroll
    for (int i = 0; i < 8; i++) {
        const int idx = tid + i * 256;
        const int nr = idx >> 5, kp = (idx & 31) * 2;
        const __half2 h = __floats2half2_rn(t[kp][nr], t[kp + 1][nr]);
        *(__half2*)(Wt + (size_t)(n0 + nr) * K + k0 + kp) = h;
    }
}

__global__ void wtrans64(const float* __restrict__ W, __half* __restrict__ Wt,
                         int K, int N)
{
    wtrans_body(W, Wt, K, N);
}

__global__ void wtrans_qkv(const float* __restrict__ Wq,
                           const float* __restrict__ Wk,
                           const float* __restrict__ Wv,
                           __half* __restrict__ Wt)
{
    const float* W = (blockIdx.z == 0) ? Wq : (blockIdx.z == 1) ? Wk : Wv;
    wtrans_body(W, Wt + (size_t)blockIdx.z * CDIM * CDIM, CDIM, CDIM);
}

// ===========================================================================
// LayerNorm -> fp16 (one block per row, 192 threads)
// ===========================================================================
__global__ void ln_half(const float* __restrict__ x, const float* __restrict__ g,
                        const float* __restrict__ b, __half* __restrict__ out)
{
    const int row = blockIdx.x;
    const int t   = threadIdx.x;
    const float4 v = ((const float4*)(x + (size_t)row * CDIM))[t];

    float s = v.x + v.y + v.z + v.w;
    float q = v.x * v.x + v.y * v.y + v.z * v.z + v.w * v.w;
    __shared__ float ss[6], sq[6];
    #pragma unroll
    for (int off = 16; off > 0; off >>= 1) {
        s += __shfl_xor_sync(0xffffffffu, s, off);
        q += __shfl_xor_sync(0xffffffffu, q, off);
    }
    if ((t & 31) == 0) { ss[t >> 5] = s; sq[t >> 5] = q; }
    __syncthreads();
    s = ss[0] + ss[1] + ss[2] + ss[3] + ss[4] + ss[5];
    q = sq[0] + sq[1] + sq[2] + sq[3] + sq[4] + sq[5];

    const float mean = s * (1.0f / CDIM);
    const float var  = q * (1.0f / CDIM) - mean * mean;
    const float rstd = rsqrtf(var + 1e-5f);

    const float4 gv = ((const float4*)g)[t];
    const float4 bv = ((const float4*)b)[t];
    __half2 o01 = __floats2half2_rn((v.x - mean) * rstd * gv.x + bv.x,
                                    (v.y - mean) * rstd * gv.y + bv.y);
    __half2 o23 = __floats2half2_rn((v.z - mean) * rstd * gv.z + bv.z,
                                    (v.w - mean) * rstd * gv.w + bv.w);
    ((__half2*)(out + (size_t)row * CDIM))[t * 2]     = o01;
    ((__half2*)(out + (size_t)row * CDIM))[t * 2 + 1] = o23;
}

// ===========================================================================
// Persistent fp16 mma.sync GEMM:  C[M,N] = A[M,K] @ B[N,K]^T
// 128x128x64 tiles, double-buffered cp.async, 8 warps, warp tile 32x64.
// Grid = NPERSIST blocks; each loops over tiles; next tile's loads issued
// before the current tile's epilogue (overlap).
// ===========================================================================
enum { EPI_HALF = 0, EPI_BIAS_RES = 1, EPI_BIAS_GELU_H = 2 };

#define BM 128
#define BN 128
#define BK 64
#define ATILE (BM * BK * 2)               // 16384 B
#define STAGE (ATILE * 2)                 // A + B = 32768 B
#define GEMM_SMEM (2 * STAGE)             // 65536 B

__device__ __forceinline__ float gelu_exact(float x) {
    return 0.5f * x * (1.0f + erff(x * 0.7071067811865475f));
}

template <int EPI>
__global__ void __launch_bounds__(256, 2)
gemm_mma(int M, int N, int K,
         const __half* __restrict__ A, const __half* __restrict__ B,
         const float* __restrict__ bias, const float* __restrict__ res,
         float* __restrict__ Cf, __half* __restrict__ Ch)
{
    extern __shared__ char smem[];
    const uint32_t sbase = smem_u32(smem);
    const int tid  = threadIdx.x;
    const int lane = tid & 31;
    const int wid  = tid >> 5;
    const int wm   = wid >> 1;
    const int wn   = wid & 1;

    const int nbx    = N / BN;
    const int ntiles = nbx * (M / BM);
    const int nst    = K / BK;
    const int lr0 = tid >> 3;
    const int lc  = (tid & 7) * 16;

    auto issue_stage = [&](int brow, int bcol, int s) {
        const int k0  = s * BK;
        const uint32_t sA = sbase + (s & 1) * STAGE;
        const uint32_t sB = sA + ATILE;
        #pragma unroll
        for (int c = 0; c < 4; c++) {
            const int row = lr0 + c * 32;
            const uint32_t so = SWZ((uint32_t)(row * 128 + lc));
            CP_ASYNC16(sA + so, A + (size_t)(brow + row) * K + k0 + (lc >> 1));
            CP_ASYNC16(sB + so, B + (size_t)(bcol + row) * K + k0 + (lc >> 1));
        }
        CP_COMMIT();
    };

    const int a_row = wm * 32 + (lane & 15);
    const int a_kb  = (lane >> 4) << 4;
    const int b_row = wn * 64 + ((lane >> 4) << 3) + (lane & 7);
    const int b_kb  = ((lane >> 3) & 1) << 4;

    // prime first tile
    if ((int)blockIdx.x < ntiles) {
        const int brow = (blockIdx.x / nbx) * BM;
        const int bcol = (blockIdx.x % nbx) * BN;
        issue_stage(brow, bcol, 0);
        issue_stage(brow, bcol, 1);
    }

    for (int t = blockIdx.x; t < ntiles; t += gridDim.x) {
        const int brow = (t / nbx) * BM;
        const int bcol = (t % nbx) * BN;

        float acc[2][8][4];
        #pragma unroll
        for (int i = 0; i < 2; i++)
            #pragma unroll
            for (int j = 0; j < 8; j++)
                #pragma unroll
                for (int c = 0; c < 4; c++) acc[i][j][c] = 0.0f;

        for (int s = 0; s < nst; s++) {
            if (s < nst - 1) CP_WAIT(1);
            else             CP_WAIT(0);
            __syncthreads();

            const uint32_t sA = sbase + (s & 1) * STAGE;
            const uint32_t sB = sA + ATILE;

            #pragma unroll
            for (int kk = 0; kk < 4; kk++) {
                uint32_t af[2][4], bf[4][4];
                #pragma unroll
                for (int mi = 0; mi < 2; mi++)
                    ldsm4(af[mi], sA + SWZ((uint32_t)((a_row + mi * 16) * 128 +
                                                      a_kb + kk * 32)));
                #pragma unroll
                for (int bj = 0; bj < 4; bj++)
                    ldsm4(bf[bj], sB + SWZ((uint32_t)((b_row + bj * 16) * 128 +
                                                      b_kb + kk * 32)));
                #pragma unroll
                for (int mi = 0; mi < 2; mi++)
                    #pragma unroll
                    for (int ni = 0; ni < 8; ni++)
                        mma16816(acc[mi][ni], af[mi],
                                 bf[ni >> 1][(ni & 1) * 2],
                                 bf[ni >> 1][(ni & 1) * 2 + 1]);
            }
            __syncthreads();
            if (s + 2 < nst) issue_stage(brow, bcol, s + 2);
        }

        // prefetch next tile's first two stages under the epilogue
        const int tn = t + gridDim.x;
        if (tn < ntiles) {
            const int nbrow = (tn / nbx) * BM;
            const int nbcol = (tn % nbx) * BN;
            issue_stage(nbrow, nbcol, 0);
            issue_stage(nbrow, nbcol, 1);
        }

        // epilogue
        const int er = brow + wm * 32 + (lane >> 2);
        const int ec = bcol + wn * 64 + (lane & 3) * 2;
        #pragma unroll
        for (int mi = 0; mi < 2; mi++) {
            #pragma unroll
            for (int half = 0; half < 2; half++) {
                const int r = er + mi * 16 + half * 8;
                #pragma unroll
                for (int ni = 0; ni < 8; ni++) {
                    const int c = ec + ni * 8;
                    const float d0 = acc[mi][ni][half * 2];
                    const float d1 = acc[mi][ni][half * 2 + 1];
                    if (EPI == EPI_HALF) {
                        *(__half2*)(Ch + (size_t)r * N + c) =
                            __floats2half2_rn(d0, d1);
                    } else if (EPI == EPI_BIAS_RES) {
                        const float2 rv = *(const float2*)(res + (size_t)r * N + c);
                        *(float2*)(Cf + (size_t)r * N + c) =
                            make_float2(d0 + bias[c] + rv.x,
                                        d1 + bias[c + 1] + rv.y);
                    } else {
                        const float a = gelu_exact(d0 + bias[c]);
                        const float b = gelu_exact(d1 + bias[c + 1]);
                        *(__half2*)(Ch + (size_t)r * N + c) =
                            __floats2half2_rn(a, b);
                    }
                }
            }
        }
    }
}

// ===========================================================================
// fp16 mma flash attention (R6 config: 128 threads, Q tile 64, KV tile 64).
// ===========================================================================
__global__ void __launch_bounds__(128)
attn_mma(const __half* __restrict__ qkv, __half* __restrict__ O)
{
    __shared__ __align__(128) char qs_raw[8192];
    __shared__ __align__(128) char ks_raw[8192];
    __shared__ __align__(128) char vs_raw[8192];
    const uint32_t qs = smem_u32(qs_raw);
    const uint32_t ks = smem_u32(ks_raw);
    const uint32_t vs = smem_u32(vs_raw);

    const int qt = blockIdx.x;
    const int bh = blockIdx.y;
    const int b  = bh / NHEAD, h = bh % NHEAD;
    const int tid = threadIdx.x, lane = tid & 31, w = tid >> 5;
    const size_t rowbase = (size_t)b * TDIM;

    #pragma unroll
    for (int c = 0; c < 4; c++) {
        const int id = tid + c * 128;
        const int r = id >> 3, col = id & 7;
        const __half* src = qkv + (rowbase + qt * 64 + r) * QKVW + h * 64 + col * 8;
        *(uint4*)(qs_raw + SWZ((uint32_t)(r * 128 + col * 16))) = *(const uint4*)src;
    }
    __syncthreads();

    uint32_t qf[4][4];
    #pragma unroll
    for (int kk = 0; kk < 4; kk++)
        ldsm4(qf[kk], qs + SWZ((uint32_t)((w * 16 + (lane & 15)) * 128 +
                                          ((lane >> 4) << 4) + kk * 32)));

    float oacc[8][4];
    #pragma unroll
    for (int i = 0; i < 8; i++)
        #pragma unroll
        for (int j = 0; j < 4; j++) oacc[i][j] = 0.0f;
    float m0 = -INFINITY, m1 = -INFINITY, l0 = 0.0f, l1 = 0.0f;
    const float scale = 0.03608439182435161f;   // 768^-0.5 (C, not hs)

    const int r0 = qt * 64 + w * 16 + (lane >> 2);
    const int r1 = r0 + 8;

    for (int jt = 0; jt <= qt; jt++) {
        __syncthreads();
        #pragma unroll
        for (int c = 0; c < 4; c++) {
            const int id = tid + c * 128;
            const int r = id >> 3, col = id & 7;
            const size_t grow = (rowbase + jt * 64 + r) * QKVW + h * 64 + col * 8;
            const uint32_t so = SWZ((uint32_t)(r * 128 + col * 16));
            *(uint4*)(ks_raw + so) = *(const uint4*)(qkv + grow + 768);
            *(uint4*)(vs_raw + so) = *(const uint4*)(qkv + grow + 1536);
        }
        __syncthreads();

        float sacc[8][4];
        #pragma unroll
        for (int i = 0; i < 8; i++)
            #pragma unroll
            for (int j = 0; j < 4; j++) sacc[i][j] = 0.0f;
        #pragma unroll
        for (int kk = 0; kk < 4; kk++) {
            uint32_t bf[4][4];
            #pragma unroll
            for (int bj = 0; bj < 4; bj++)
                ldsm4(bf[bj], ks + SWZ((uint32_t)(
                    (((lane >> 4) << 3) + (lane & 7) + bj * 16) * 128 +
                    (((lane >> 3) & 1) << 4) + kk * 32)));
            #pragma unroll
            for (int ni = 0; ni < 8; ni++)
                mma16816(sacc[ni], qf[kk],
                         bf[ni >> 1][(ni & 1) * 2],
                         bf[ni >> 1][(ni & 1) * 2 + 1]);
        }

        #pragma unroll
        for (int ni = 0; ni < 8; ni++) {
            const int c = jt * 64 + ni * 8 + (lane & 3) * 2;
            sacc[ni][0] = (c     <= r0) ? sacc[ni][0] * scale : -1e30f;
            sacc[ni][1] = (c + 1 <= r0) ? sacc[ni][1] * scale : -1e30f;
            sacc[ni][2] = (c     <= r1) ? sacc[ni][2] * scale : -1e30f;
            sacc[ni][3] = (c + 1 <= r1) ? sacc[ni][3] * scale : -1e30f;
        }

        float mx0 = -INFINITY, mx1 = -INFINITY;
        #pragma unroll
        for (int ni = 0; ni < 8; ni++) {
            mx0 = fmaxf(mx0, fmaxf(sacc[ni][0], sacc[ni][1]));
            mx1 = fmaxf(mx1, fmaxf(sacc[ni][2], sacc[ni][3]));
        }
        #pragma unroll
        for (int off = 1; off < 4; off <<= 1) {
            mx0 = fmaxf(mx0, __shfl_xor_sync(0xffffffffu, mx0, off));
            mx1 = fmaxf(mx1, __shfl_xor_sync(0xffffffffu, mx1, off));
        }
        const float m0n = fmaxf(m0, mx0), m1n = fmaxf(m1, mx1);
        const float a0 = __expf(m0 - m0n), a1 = __expf(m1 - m1n);
        m0 = m0n; m1 = m1n;

        float rs0 = 0.0f, rs1 = 0.0f;
        uint32_t pf[8][2];
        #pragma unroll
        for (int ni = 0; ni < 8; ni++) {
            const float p0 = __expf(sacc[ni][0] - m0n);
            const float p1 = __expf(sacc[ni][1] - m0n);
            const float p2 = __expf(sacc[ni][2] - m1n);
            const float p3 = __expf(sacc[ni][3] - m1n);
            rs0 += p0 + p1; rs1 += p2 + p3;
            pf[ni][0] = pack_h2(p0, p1);
            pf[ni][1] = pack_h2(p2, p3);
        }
        #pragma unroll
        for (int off = 1; off < 4; off <<= 1) {
            rs0 += __shfl_xor_sync(0xffffffffu, rs0, off);
            rs1 += __shfl_xor_sync(0xffffffffu, rs1, off);
        }
        l0 = l0 * a0 + rs0;
        l1 = l1 * a1 + rs1;
        #pragma unroll
        for (int ni = 0; ni < 8; ni++) {
            oacc[ni][0] *= a0; oacc[ni][1] *= a0;
            oacc[ni][2] *= a1; oacc[ni][3] *= a1;
        }

        #pragma unroll
        for (int kk = 0; kk < 4; kk++) {
            uint32_t a[4] = { pf[2 * kk][0], pf[2 * kk][1],
                              pf[2 * kk + 1][0], pf[2 * kk + 1][1] };
            #pragma unroll
            for (int vb = 0; vb < 4; vb++) {
                uint32_t bv[4];
                ldsm4t(bv, vs + SWZ((uint32_t)(
                    (kk * 16 + ((lane >> 3) & 1) * 8 + (lane & 7)) * 128 +
                    ((lane >> 4) & 1) * 16 + vb * 32)));
                mma16816(oacc[vb * 2],     a, bv[0], bv[1]);
                mma16816(oacc[vb * 2 + 1], a, bv[2], bv[3]);
            }
        }
    }

    const float il0 = 1.0f / l0, il1 = 1.0f / l1;
    const int orow = qt * 64 + w * 16 + (lane >> 2);
    #pragma unroll
    for (int ni = 0; ni < 8; ni++) {
        const int col = h * 64 + ni * 8 + (lane & 3) * 2;
        *(__half2*)(O + (rowbase + orow) * CDIM + col) =
            __floats2half2_rn(oacc[ni][0] * il0, oacc[ni][1] * il0);
        *(__half2*)(O + (rowbase + orow + 8) * CDIM + col) =
            __floats2half2_rn(oacc[ni][2] * il1, oacc[ni][3] * il1);
    }
}

// ===========================================================================
// Launch  (order: ncu profiles our launch index 3 => QKV GEMM)
// ===========================================================================
extern "C" void kernel_launch(void* const* d_in, const int* in_sizes, int n_in,
                              void* d_out, int out_size)
{
    const float* x   = (const float*)d_in[0];
    const float* Wq  = (const float*)d_in[1];
    const float* Wk  = (const float*)d_in[2];
    const float* Wv  = (const float*)d_in[3];
    const float* Wo  = (const float*)d_in[4];
    const float* bo  = (const float*)d_in[5];
    const float* W1  = (const float*)d_in[6];
    const float* b1  = (const float*)d_in[7];
    const float* W2  = (const float*)d_in[8];
    const float* b2  = (const float*)d_in[9];
    const float* g1  = (const float*)d_in[10];
    const float* be1 = (const float*)d_in[11];
    const float* g2  = (const float*)d_in[12];
    const float* be2 = (const float*)d_in[13];
    float* out = (float*)d_out;

    __half *h, *qkv, *att, *h2, *ff, *wqkv, *wo, *w1, *w2;
    float *x2;
    cudaGetSymbolAddress((void**)&h,    g_h);
    cudaGetSymbolAddress((void**)&qkv,  g_qkv);
    cudaGetSymbolAddress((void**)&att,  g_att);
    cudaGetSymbolAddress((void**)&h2,   g_h2);
    cudaGetSymbolAddress((void**)&ff,   g_ff);
    cudaGetSymbolAddress((void**)&wqkv, g_Wqkv);
    cudaGetSymbolAddress((void**)&wo,   g_Wo);
    cudaGetSymbolAddress((void**)&w1,   g_W1);
    cudaGetSymbolAddress((void**)&w2,   g_W2);
    cudaGetSymbolAddress((void**)&x2,   g_x2);

    cudaFuncSetAttribute((const void*)gemm_mma<EPI_HALF>,
                         cudaFuncAttributeMaxDynamicSharedMemorySize, GEMM_SMEM);
    cudaFuncSetAttribute((const void*)gemm_mma<EPI_BIAS_RES>,
                         cudaFuncAttributeMaxDynamicSharedMemorySize, GEMM_SMEM);
    cudaFuncSetAttribute((const void*)gemm_mma<EPI_BIAS_GELU_H>,
                         cudaFuncAttributeMaxDynamicSharedMemorySize, GEMM_SMEM);

    auto pgrid = [](int ntiles) { return ntiles < NPERSIST ? ntiles : NPERSIST; };

    // 0: fused QKV weight transpose
    wtrans_qkv<<<dim3(CDIM / 64, CDIM / 64, 3), 256>>>(Wq, Wk, Wv, wqkv);
    // 1: Wo transpose
    wtrans64<<<dim3(CDIM / 64, CDIM / 64), 256>>>(Wo, wo, CDIM, CDIM);
    // 2: LN1
    ln_half<<<MROWS, 192>>>(x, g1, be1, h);
    // 3: fused QKV GEMM  <- profiled by ncu
    gemm_mma<EPI_HALF><<<pgrid((QKVW / BN) * (MROWS / BM)), 256, GEMM_SMEM>>>(
        MROWS, QKVW, CDIM, h, wqkv, nullptr, nullptr, nullptr, qkv);
    // 4: attention
    attn_mma<<<dim3(TDIM / 64, BDIM * NHEAD), 128>>>(qkv, att);
    // 5: x2 = x + att @ Wo + bo
    gemm_mma<EPI_BIAS_RES><<<pgrid((CDIM / BN) * (MROWS / BM)), 256, GEMM_SMEM>>>(
        MROWS, CDIM, CDIM, att, wo, bo, x, x2, nullptr);
    // 6: LN2
    ln_half<<<MROWS, 192>>>(x2, g2, be2, h2);
    // 7: W1 transpose,  8: ff = gelu(h2 @ W1 + b1)
    wtrans64<<<dim3(FDIM / 64, CDIM / 64), 256>>>(W1, w1, CDIM, FDIM);
    gemm_mma<EPI_BIAS_GELU_H><<<pgrid((FDIM / BN) * (MROWS / BM)), 256, GEMM_SMEM>>>(
        MROWS, FDIM, CDIM, h2, w1, b1, nullptr, nullptr, ff);
    // 9: W2 transpose, 10: out = x2 + ff @ W2 + b2
    wtrans64<<<dim3(CDIM / 64, FDIM / 64), 256>>>(W2, w2, FDIM, CDIM);
    gemm_mma<EPI_BIAS_RES><<<pgrid((CDIM / BN) * (MROWS / BM)), 256, GEMM_SMEM>>>(
        MROWS, CDIM, FDIM, ff, w2, b2, x2, out, nullptr);
}

// round 15
// speedup vs baseline: 1.0291x; 1.0291x over previous
#include <cuda_runtime.h>
#include <cuda_fp16.h>
#include <math.h>
#include <stdint.h>

#define CDIM  768
#define TDIM  1024
#define BDIM  8
#define MROWS 8192
#define FDIM  3072
#define NHEAD 12
#define HSIZE 64
#define QKVW  2304

// ===========================================================================
// Scratch (no cudaMalloc allowed)
// ===========================================================================
__device__ __half g_h   [MROWS * CDIM];
__device__ __half g_qkv [MROWS * QKVW];
__device__ __half g_att [MROWS * CDIM];
__device__ __half g_h2  [MROWS * CDIM];
__device__ __half g_ff  [MROWS * FDIM];
__device__ float  g_x2  [MROWS * CDIM];
__device__ __half g_Wqkv[QKVW * CDIM];
__device__ __half g_Wo  [CDIM * CDIM];
__device__ __half g_W1  [CDIM * FDIM];
__device__ __half g_W2  [FDIM * CDIM];

__device__ __forceinline__ uint32_t smem_u32(const void* p) {
    uint32_t a;
    asm("{ .reg .u64 t; cvta.to.shared.u64 t, %1; cvt.u32.u64 %0, t; }"
        : "=r"(a) : "l"(p));
    return a;
}
#define SWZ(off) ((off) ^ (((off) >> 3) & 0x70))

__device__ __forceinline__ void ldsm4(uint32_t* r, uint32_t addr) {
    asm volatile("ldmatrix.sync.aligned.m8n8.x4.shared.b16 {%0,%1,%2,%3}, [%4];"
                 : "=r"(r[0]), "=r"(r[1]), "=r"(r[2]), "=r"(r[3]) : "r"(addr));
}
__device__ __forceinline__ void ldsm4t(uint32_t* r, uint32_t addr) {
    asm volatile("ldmatrix.sync.aligned.m8n8.x4.trans.shared.b16 {%0,%1,%2,%3}, [%4];"
                 : "=r"(r[0]), "=r"(r[1]), "=r"(r[2]), "=r"(r[3]) : "r"(addr));
}
__device__ __forceinline__ void mma16816(float* d, const uint32_t* a,
                                         uint32_t b0, uint32_t b1) {
    asm volatile("mma.sync.aligned.m16n8k16.row.col.f32.f16.f16.f32 "
                 "{%0,%1,%2,%3}, {%4,%5,%6,%7}, {%8,%9}, {%0,%1,%2,%3};"
                 : "+f"(d[0]), "+f"(d[1]), "+f"(d[2]), "+f"(d[3])
                 : "r"(a[0]), "r"(a[1]), "r"(a[2]), "r"(a[3]), "r"(b0), "r"(b1));
}
__device__ __forceinline__ uint32_t pack_h2(float a, float b) {
    __half2 h = __floats2half2_rn(a, b);
    return *(uint32_t*)&h;
}
#define CP_ASYNC16(dst, src) \
    asm volatile("cp.async.cg.shared.global [%0], [%1], 16;" :: "r"(dst), "l"(src))
#define CP_COMMIT() asm volatile("cp.async.commit_group;" ::: "memory")
#define CP_WAIT(n)  asm volatile("cp.async.wait_group %0;" :: "n"(n) : "memory")

// ===========================================================================
// Fused weight transpose:  all W[K,N] fp32 -> Wt[N,K] fp16 in ONE launch.
// 64x64 tiles, 256 threads. 1728 tile-blocks decoded from blockIdx.x.
// ===========================================================================
__device__ __forceinline__ void wtrans_tile(const float* __restrict__ W,
                                            __half* __restrict__ Wt,
                                            int K, int N, int n0, int k0)
{
    __shared__ float t[64][65];
    const int tid = threadIdx.x;
    #pragma unroll
    for (int i = 0; i < 4; i++) {
        const int idx = tid + i * 256;
        const int kr = idx >> 4, nc = (idx & 15) * 4;
        const float4 v = *(const float4*)(W + (size_t)(k0 + kr) * N + n0 + nc);
        t[kr][nc] = v.x; t[kr][nc + 1] = v.y; t[kr][nc + 2] = v.z; t[kr][nc + 3] = v.w;
    }
    __syncthreads();
    #pragma unroll
    for (int i = 0; i < 8; i++) {
        const int idx = tid + i * 256;
        const int nr = idx >> 5, kp = (idx & 31) * 2;
        const __half2 h = __floats2half2_rn(t[kp][nr], t[kp + 1][nr]);
        *(__half2*)(Wt + (size_t)(n0 + nr) * K + k0 + kp) = h;
    }
}

__global__ void wtrans_all(const float* __restrict__ Wq,
                           const float* __restrict__ Wk,
                           const float* __restrict__ Wv,
                           const float* __restrict__ Wo,
                           const float* __restrict__ W1,
                           const float* __restrict__ W2,
                           __half* __restrict__ wqkv, __half* __restrict__ wo,
                           __half* __restrict__ w1,   __half* __restrict__ w2)
{
    const int t = blockIdx.x;
    if (t < 432) {                         // Wq/Wk/Wv: 3 x (12x12) tiles
        const int z = t / 144, r = t % 144;
        const float* W = (z == 0) ? Wq : (z == 1) ? Wk : Wv;
        wtrans_tile(W, wqkv + (size_t)z * CDIM * CDIM, CDIM, CDIM,
                    (r % 12) * 64, (r / 12) * 64);
    } else if (t < 576) {                  // Wo: 12x12
        const int r = t - 432;
        wtrans_tile(Wo, wo, CDIM, CDIM, (r % 12) * 64, (r / 12) * 64);
    } else if (t < 1152) {                 // W1 [768,3072]: 48x12
        const int r = t - 576;
        wtrans_tile(W1, w1, CDIM, FDIM, (r % 48) * 64, (r / 48) * 64);
    } else {                               // W2 [3072,768]: 12x48
        const int r = t - 1152;
        wtrans_tile(W2, w2, FDIM, CDIM, (r % 12) * 64, (r / 12) * 64);
    }
}
#define WTRANS_BLOCKS 1728

// ===========================================================================
// LayerNorm -> fp16 (one block per row, 192 threads)
// ===========================================================================
__global__ void ln_half(const float* __restrict__ x, const float* __restrict__ g,
                        const float* __restrict__ b, __half* __restrict__ out)
{
    const int row = blockIdx.x;
    const int t   = threadIdx.x;
    const float4 v = ((const float4*)(x + (size_t)row * CDIM))[t];

    float s = v.x + v.y + v.z + v.w;
    float q = v.x * v.x + v.y * v.y + v.z * v.z + v.w * v.w;
    __shared__ float ss[6], sq[6];
    #pragma unroll
    for (int off = 16; off > 0; off >>= 1) {
        s += __shfl_xor_sync(0xffffffffu, s, off);
        q += __shfl_xor_sync(0xffffffffu, q, off);
    }
    if ((t & 31) == 0) { ss[t >> 5] = s; sq[t >> 5] = q; }
    __syncthreads();
    s = ss[0] + ss[1] + ss[2] + ss[3] + ss[4] + ss[5];
    q = sq[0] + sq[1] + sq[2] + sq[3] + sq[4] + sq[5];

    const float mean = s * (1.0f / CDIM);
    const float var  = q * (1.0f / CDIM) - mean * mean;
    const float rstd = rsqrtf(var + 1e-5f);

    const float4 gv = ((const float4*)g)[t];
    const float4 bv = ((const float4*)b)[t];
    __half2 o01 = __floats2half2_rn((v.x - mean) * rstd * gv.x + bv.x,
                                    (v.y - mean) * rstd * gv.y + bv.y);
    __half2 o23 = __floats2half2_rn((v.z - mean) * rstd * gv.z + bv.z,
                                    (v.w - mean) * rstd * gv.w + bv.w);
    ((__half2*)(out + (size_t)row * CDIM))[t * 2]     = o01;
    ((__half2*)(out + (size_t)row * CDIM))[t * 2 + 1] = o23;
}

// ===========================================================================
// fp16 mma.sync GEMM (R10 proven config):  C[M,N] = A[M,K] @ B[N,K]^T
// 128x128x64 tiles, double-buffered cp.async, 8 warps (4x2), warp tile 32x64.
// ===========================================================================
enum { EPI_HALF = 0, EPI_BIAS_RES = 1, EPI_BIAS_GELU_H = 2 };

#define BM 128
#define BN 128
#define BK 64
#define ATILE (BM * BK * 2)               // 16384 B
#define STAGE (ATILE * 2)                 // A + B = 32768 B
#define GEMM_SMEM (2 * STAGE)             // 65536 B

__device__ __forceinline__ float gelu_exact(float x) {
    return 0.5f * x * (1.0f + erff(x * 0.7071067811865475f));
}

template <int EPI>
__global__ void __launch_bounds__(256)
gemm_mma(int M, int N, int K,
         const __half* __restrict__ A, const __half* __restrict__ B,
         const float* __restrict__ bias, const float* __restrict__ res,
         float* __restrict__ Cf, __half* __restrict__ Ch)
{
    extern __shared__ char smem[];
    const uint32_t sbase = smem_u32(smem);
    const int tid  = threadIdx.x;
    const int lane = tid & 31;
    const int wid  = tid >> 5;
    const int wm   = wid >> 1;
    const int wn   = wid & 1;
    const int brow = blockIdx.y * BM, bcol = blockIdx.x * BN;

    float acc[2][8][4];
    #pragma unroll
    for (int i = 0; i < 2; i++)
        #pragma unroll
        for (int j = 0; j < 8; j++)
            #pragma unroll
            for (int c = 0; c < 4; c++) acc[i][j][c] = 0.0f;

    const int nst = K / BK;
    const int lr0 = tid >> 3;
    const int lc  = (tid & 7) * 16;

    auto issue_stage = [&](int s) {
        const int k0  = s * BK;
        const uint32_t sA = sbase + (s & 1) * STAGE;
        const uint32_t sB = sA + ATILE;
        #pragma unroll
        for (int c = 0; c < 4; c++) {
            const int row = lr0 + c * 32;
            const uint32_t so = SWZ((uint32_t)(row * 128 + lc));
            CP_ASYNC16(sA + so, A + (size_t)(brow + row) * K + k0 + (lc >> 1));
            CP_ASYNC16(sB + so, B + (size_t)(bcol + row) * K + k0 + (lc >> 1));
        }
        CP_COMMIT();
    };

    issue_stage(0);
    issue_stage(1);

    const int a_row = wm * 32 + (lane & 15);
    const int a_kb  = (lane >> 4) << 4;
    const int b_row = wn * 64 + ((lane >> 4) << 3) + (lane & 7);
    const int b_kb  = ((lane >> 3) & 1) << 4;

    for (int s = 0; s < nst; s++) {
        if (s < nst - 1) CP_WAIT(1);
        else             CP_WAIT(0);
        __syncthreads();

        const uint32_t sA = sbase + (s & 1) * STAGE;
        const uint32_t sB = sA + ATILE;

        #pragma unroll
        for (int kk = 0; kk < 4; kk++) {
            uint32_t af[2][4], bf[4][4];
            #pragma unroll
            for (int mi = 0; mi < 2; mi++)
                ldsm4(af[mi], sA + SWZ((uint32_t)((a_row + mi * 16) * 128 +
                                                  a_kb + kk * 32)));
            #pragma unroll
            for (int bj = 0; bj < 4; bj++)
                ldsm4(bf[bj], sB + SWZ((uint32_t)((b_row + bj * 16) * 128 +
                                                  b_kb + kk * 32)));
            #pragma unroll
            for (int mi = 0; mi < 2; mi++)
                #pragma unroll
                for (int ni = 0; ni < 8; ni++)
                    mma16816(acc[mi][ni], af[mi],
                             bf[ni >> 1][(ni & 1) * 2],
                             bf[ni >> 1][(ni & 1) * 2 + 1]);
        }
        __syncthreads();
        if (s + 2 < nst) issue_stage(s + 2);
    }

    const int er = brow + wm * 32 + (lane >> 2);
    const int ec = bcol + wn * 64 + (lane & 3) * 2;
    #pragma unroll
    for (int mi = 0; mi < 2; mi++) {
        #pragma unroll
        for (int half = 0; half < 2; half++) {
            const int r = er + mi * 16 + half * 8;
            #pragma unroll
            for (int ni = 0; ni < 8; ni++) {
                const int c = ec + ni * 8;
                const float d0 = acc[mi][ni][half * 2];
                const float d1 = acc[mi][ni][half * 2 + 1];
                if (EPI == EPI_HALF) {
                    *(__half2*)(Ch + (size_t)r * N + c) = __floats2half2_rn(d0, d1);
                } else if (EPI == EPI_BIAS_RES) {
                    const float2 rv = *(const float2*)(res + (size_t)r * N + c);
                    *(float2*)(Cf + (size_t)r * N + c) =
                        make_float2(d0 + bias[c] + rv.x, d1 + bias[c + 1] + rv.y);
                } else {
                    const float a = gelu_exact(d0 + bias[c]);
                    const float b = gelu_exact(d1 + bias[c + 1]);
                    *(__half2*)(Ch + (size_t)r * N + c) = __floats2half2_rn(a, b);
                }
            }
        }
    }
}

// ===========================================================================
// fp16 mma flash attention (R6 config: 128 threads, Q tile 64, KV tile 64).
// ===========================================================================
__global__ void __launch_bounds__(128)
attn_mma(const __half* __restrict__ qkv, __half* __restrict__ O)
{
    __shared__ __align__(128) char qs_raw[8192];
    __shared__ __align__(128) char ks_raw[8192];
    __shared__ __align__(128) char vs_raw[8192];
    const uint32_t qs = smem_u32(qs_raw);
    const uint32_t ks = smem_u32(ks_raw);
    const uint32_t vs = smem_u32(vs_raw);

    const int qt = blockIdx.x;
    const int bh = blockIdx.y;
    const int b  = bh / NHEAD, h = bh % NHEAD;
    const int tid = threadIdx.x, lane = tid & 31, w = tid >> 5;
    const size_t rowbase = (size_t)b * TDIM;

    #pragma unroll
    for (int c = 0; c < 4; c++) {
        const int id = tid + c * 128;
        const int r = id >> 3, col = id & 7;
        const __half* src = qkv + (rowbase + qt * 64 + r) * QKVW + h * 64 + col * 8;
        *(uint4*)(qs_raw + SWZ((uint32_t)(r * 128 + col * 16))) = *(const uint4*)src;
    }
    __syncthreads();

    uint32_t qf[4][4];
    #pragma unroll
    for (int kk = 0; kk < 4; kk++)
        ldsm4(qf[kk], qs + SWZ((uint32_t)((w * 16 + (lane & 15)) * 128 +
                                          ((lane >> 4) << 4) + kk * 32)));

    float oacc[8][4];
    #pragma unroll
    for (int i = 0; i < 8; i++)
        #pragma unroll
        for (int j = 0; j < 4; j++) oacc[i][j] = 0.0f;
    float m0 = -INFINITY, m1 = -INFINITY, l0 = 0.0f, l1 = 0.0f;
    const float scale = 0.03608439182435161f;   // 768^-0.5 (C, not hs)

    const int r0 = qt * 64 + w * 16 + (lane >> 2);
    const int r1 = r0 + 8;

    for (int jt = 0; jt <= qt; jt++) {
        __syncthreads();
        #pragma unroll
        for (int c = 0; c < 4; c++) {
            const int id = tid + c * 128;
            const int r = id >> 3, col = id & 7;
            const size_t grow = (rowbase + jt * 64 + r) * QKVW + h * 64 + col * 8;
            const uint32_t so = SWZ((uint32_t)(r * 128 + col * 16));
            *(uint4*)(ks_raw + so) = *(const uint4*)(qkv + grow + 768);
            *(uint4*)(vs_raw + so) = *(const uint4*)(qkv + grow + 1536);
        }
        __syncthreads();

        float sacc[8][4];
        #pragma unroll
        for (int i = 0; i < 8; i++)
            #pragma unroll
            for (int j = 0; j < 4; j++) sacc[i][j] = 0.0f;
        #pragma unroll
        for (int kk = 0; kk < 4; kk++) {
            uint32_t bf[4][4];
            #pragma unroll
            for (int bj = 0; bj < 4; bj++)
                ldsm4(bf[bj], ks + SWZ((uint32_t)(
                    (((lane >> 4) << 3) + (lane & 7) + bj * 16) * 128 +
                    (((lane >> 3) & 1) << 4) + kk * 32)));
            #pragma unroll
            for (int ni = 0; ni < 8; ni++)
                mma16816(sacc[ni], qf[kk],
                         bf[ni >> 1][(ni & 1) * 2],
                         bf[ni >> 1][(ni & 1) * 2 + 1]);
        }

        #pragma unroll
        for (int ni = 0; ni < 8; ni++) {
            const int c = jt * 64 + ni * 8 + (lane & 3) * 2;
            sacc[ni][0] = (c     <= r0) ? sacc[ni][0] * scale : -1e30f;
            sacc[ni][1] = (c + 1 <= r0) ? sacc[ni][1] * scale : -1e30f;
            sacc[ni][2] = (c     <= r1) ? sacc[ni][2] * scale : -1e30f;
            sacc[ni][3] = (c + 1 <= r1) ? sacc[ni][3] * scale : -1e30f;
        }

        float mx0 = -INFINITY, mx1 = -INFINITY;
        #pragma unroll
        for (int ni = 0; ni < 8; ni++) {
            mx0 = fmaxf(mx0, fmaxf(sacc[ni][0], sacc[ni][1]));
            mx1 = fmaxf(mx1, fmaxf(sacc[ni][2], sacc[ni][3]));
        }
        #pragma unroll
        for (int off = 1; off < 4; off <<= 1) {
            mx0 = fmaxf(mx0, __shfl_xor_sync(0xffffffffu, mx0, off));
            mx1 = fmaxf(mx1, __shfl_xor_sync(0xffffffffu, mx1, off));
        }
        const float m0n = fmaxf(m0, mx0), m1n = fmaxf(m1, mx1);
        const float a0 = __expf(m0 - m0n), a1 = __expf(m1 - m1n);
        m0 = m0n; m1 = m1n;

        float rs0 = 0.0f, rs1 = 0.0f;
        uint32_t pf[8][2];
        #pragma unroll
        for (int ni = 0; ni < 8; ni++) {
            const float p0 = __expf(sacc[ni][0] - m0n);
            const float p1 = __expf(sacc[ni][1] - m0n);
            const float p2 = __expf(sacc[ni][2] - m1n);
            const float p3 = __expf(sacc[ni][3] - m1n);
            rs0 += p0 + p1; rs1 += p2 + p3;
            pf[ni][0] = pack_h2(p0, p1);
            pf[ni][1] = pack_h2(p2, p3);
        }
        #pragma unroll
        for (int off = 1; off < 4; off <<= 1) {
            rs0 += __shfl_xor_sync(0xffffffffu, rs0, off);
            rs1 += __shfl_xor_sync(0xffffffffu, rs1, off);
        }
        l0 = l0 * a0 + rs0;
        l1 = l1 * a1 + rs1;
        #pragma unroll
        for (int ni = 0; ni < 8; ni++) {
            oacc[ni][0] *= a0; oacc[ni][1] *= a0;
            oacc[ni][2] *= a1; oacc[ni][3] *= a1;
        }

        #pragma unroll
        for (int kk = 0; kk < 4; kk++) {
            uint32_t a[4] = { pf[2 * kk][0], pf[2 * kk][1],
                              pf[2 * kk + 1][0], pf[2 * kk + 1][1] };
            #pragma unroll
            for (int vb = 0; vb < 4; vb++) {
                uint32_t bv[4];
                ldsm4t(bv, vs + SWZ((uint32_t)(
                    (kk * 16 + ((lane >> 3) & 1) * 8 + (lane & 7)) * 128 +
                    ((lane >> 4) & 1) * 16 + vb * 32)));
                mma16816(oacc[vb * 2],     a, bv[0], bv[1]);
                mma16816(oacc[vb * 2 + 1], a, bv[2], bv[3]);
            }
        }
    }

    const float il0 = 1.0f / l0, il1 = 1.0f / l1;
    const int orow = qt * 64 + w * 16 + (lane >> 2);
    #pragma unroll
    for (int ni = 0; ni < 8; ni++) {
        const int col = h * 64 + ni * 8 + (lane & 3) * 2;
        *(__half2*)(O + (rowbase + orow) * CDIM + col) =
            __floats2half2_rn(oacc[ni][0] * il0, oacc[ni][1] * il0);
        *(__half2*)(O + (rowbase + orow + 8) * CDIM + col) =
            __floats2half2_rn(oacc[ni][2] * il1, oacc[ni][3] * il1);
    }
}

// ===========================================================================
// Launch  (our launch index 3 = attention => profiled by ncu this round)
// ===========================================================================
extern "C" void kernel_launch(void* const* d_in, const int* in_sizes, int n_in,
                              void* d_out, int out_size)
{
    const float* x   = (const float*)d_in[0];
    const float* Wq  = (const float*)d_in[1];
    const float* Wk  = (const float*)d_in[2];
    const float* Wv  = (const float*)d_in[3];
    const float* Wo  = (const float*)d_in[4];
    const float* bo  = (const float*)d_in[5];
    const float* W1  = (const float*)d_in[6];
    const float* b1  = (const float*)d_in[7];
    const float* W2  = (const float*)d_in[8];
    const float* b2  = (const float*)d_in[9];
    const float* g1  = (const float*)d_in[10];
    const float* be1 = (const float*)d_in[11];
    const float* g2  = (const float*)d_in[12];
    const float* be2 = (const float*)d_in[13];
    float* out = (float*)d_out;

    __half *h, *qkv, *att, *h2, *ff, *wqkv, *wo, *w1, *w2;
    float *x2;
    cudaGetSymbolAddress((void**)&h,    g_h);
    cudaGetSymbolAddress((void**)&qkv,  g_qkv);
    cudaGetSymbolAddress((void**)&att,  g_att);
    cudaGetSymbolAddress((void**)&h2,   g_h2);
    cudaGetSymbolAddress((void**)&ff,   g_ff);
    cudaGetSymbolAddress((void**)&wqkv, g_Wqkv);
    cudaGetSymbolAddress((void**)&wo,   g_Wo);
    cudaGetSymbolAddress((void**)&w1,   g_W1);
    cudaGetSymbolAddress((void**)&w2,   g_W2);
    cudaGetSymbolAddress((void**)&x2,   g_x2);

    cudaFuncSetAttribute((const void*)gemm_mma<EPI_HALF>,
                         cudaFuncAttributeMaxDynamicSharedMemorySize, GEMM_SMEM);
    cudaFuncSetAttribute((const void*)gemm_mma<EPI_BIAS_RES>,
                         cudaFuncAttributeMaxDynamicSharedMemorySize, GEMM_SMEM);
    cudaFuncSetAttribute((const void*)gemm_mma<EPI_BIAS_GELU_H>,
                         cudaFuncAttributeMaxDynamicSharedMemorySize, GEMM_SMEM);

    // 0: ALL weight transposes in one launch
    wtrans_all<<<WTRANS_BLOCKS, 256>>>(Wq, Wk, Wv, Wo, W1, W2, wqkv, wo, w1, w2);
    // 1: LN1
    ln_half<<<MROWS, 192>>>(x, g1, be1, h);
    // 2: fused QKV GEMM
    gemm_mma<EPI_HALF><<<dim3(QKVW / BN, MROWS / BM), 256, GEMM_SMEM>>>(
        MROWS, QKVW, CDIM, h, wqkv, nullptr, nullptr, nullptr, qkv);
    // 3: attention  <- profiled by ncu this round
    attn_mma<<<dim3(TDIM / 64, BDIM * NHEAD), 128>>>(qkv, att);
    // 4: x2 = x + att @ Wo + bo
    gemm_mma<EPI_BIAS_RES><<<dim3(CDIM / BN, MROWS / BM), 256, GEMM_SMEM>>>(
        MROWS, CDIM, CDIM, att, wo, bo, x, x2, nullptr);
    // 5: LN2
    ln_half<<<MROWS, 192>>>(x2, g2, be2, h2);
    // 6: ff = gelu(h2 @ W1 + b1)
    gemm_mma<EPI_BIAS_GELU_H><<<dim3(FDIM / BN, MROWS / BM), 256, GEMM_SMEM>>>(
        MROWS, FDIM, CDIM, h2, w1, b1, nullptr, nullptr, ff);
    // 7: out = x2 + ff @ W2 + b2
    gemm_mma<EPI_BIAS_RES><<<dim3(CDIM / BN, MROWS / BM), 256, GEMM_SMEM>>>(
        MROWS, CDIM, FDIM, ff, w2, b2, x2, out, nullptr);
}

// round 16
// speedup vs baseline: 1.0377x; 1.0084x over previous
#include <cuda_runtime.h>
#include <cuda_fp16.h>
#include <math.h>
#include <stdint.h>

#define CDIM  768
#define TDIM  1024
#define BDIM  8
#define MROWS 8192
#define FDIM  3072
#define NHEAD 12
#define HSIZE 64
#define QKVW  2304
// 768^-0.5 * log2(e): Q pre-scale so softmax runs in exp2 domain
#define QSCALE 0.05205877179033723f

// ===========================================================================
// Scratch (no cudaMalloc allowed)
// ===========================================================================
__device__ __half g_h   [MROWS * CDIM];
__device__ __half g_qkv [MROWS * QKVW];
__device__ __half g_att [MROWS * CDIM];
__device__ __half g_h2  [MROWS * CDIM];
__device__ __half g_ff  [MROWS * FDIM];
__device__ float  g_x2  [MROWS * CDIM];
__device__ __half g_Wqkv[QKVW * CDIM];
__device__ __half g_Wo  [CDIM * CDIM];
__device__ __half g_W1  [CDIM * FDIM];
__device__ __half g_W2  [FDIM * CDIM];

__device__ __forceinline__ uint32_t smem_u32(const void* p) {
    uint32_t a;
    asm("{ .reg .u64 t; cvta.to.shared.u64 t, %1; cvt.u32.u64 %0, t; }"
        : "=r"(a) : "l"(p));
    return a;
}
#define SWZ(off) ((off) ^ (((off) >> 3) & 0x70))

__device__ __forceinline__ void ldsm4(uint32_t* r, uint32_t addr) {
    asm volatile("ldmatrix.sync.aligned.m8n8.x4.shared.b16 {%0,%1,%2,%3}, [%4];"
                 : "=r"(r[0]), "=r"(r[1]), "=r"(r[2]), "=r"(r[3]) : "r"(addr));
}
__device__ __forceinline__ void ldsm4t(uint32_t* r, uint32_t addr) {
    asm volatile("ldmatrix.sync.aligned.m8n8.x4.trans.shared.b16 {%0,%1,%2,%3}, [%4];"
                 : "=r"(r[0]), "=r"(r[1]), "=r"(r[2]), "=r"(r[3]) : "r"(addr));
}
__device__ __forceinline__ void mma16816(float* d, const uint32_t* a,
                                         uint32_t b0, uint32_t b1) {
    asm volatile("mma.sync.aligned.m16n8k16.row.col.f32.f16.f16.f32 "
                 "{%0,%1,%2,%3}, {%4,%5,%6,%7}, {%8,%9}, {%0,%1,%2,%3};"
                 : "+f"(d[0]), "+f"(d[1]), "+f"(d[2]), "+f"(d[3])
                 : "r"(a[0]), "r"(a[1]), "r"(a[2]), "r"(a[3]), "r"(b0), "r"(b1));
}
__device__ __forceinline__ uint32_t pack_h2(float a, float b) {
    __half2 h = __floats2half2_rn(a, b);
    return *(uint32_t*)&h;
}
__device__ __forceinline__ float ex2(float x) {
    float r;
    asm("ex2.approx.f32 %0, %1;" : "=f"(r) : "f"(x));
    return r;
}
#define CP_ASYNC16(dst, src) \
    asm volatile("cp.async.cg.shared.global [%0], [%1], 16;" :: "r"(dst), "l"(src))
#define CP_COMMIT() asm volatile("cp.async.commit_group;" ::: "memory")
#define CP_WAIT(n)  asm volatile("cp.async.wait_group %0;" :: "n"(n) : "memory")

// ===========================================================================
// Fused weight transpose:  all W[K,N] fp32 -> Wt[N,K] fp16 in ONE launch.
// ===========================================================================
__device__ __forceinline__ void wtrans_tile(const float* __restrict__ W,
                                            __half* __restrict__ Wt,
                                            int K, int N, int n0, int k0)
{
    __shared__ float t[64][65];
    const int tid = threadIdx.x;
    #pragma unroll
    for (int i = 0; i < 4; i++) {
        const int idx = tid + i * 256;
        const int kr = idx >> 4, nc = (idx & 15) * 4;
        const float4 v = *(const float4*)(W + (size_t)(k0 + kr) * N + n0 + nc);
        t[kr][nc] = v.x; t[kr][nc + 1] = v.y; t[kr][nc + 2] = v.z; t[kr][nc + 3] = v.w;
    }
    __syncthreads();
    #pragma unroll
    for (int i = 0; i < 8; i++) {
        const int idx = tid + i * 256;
        const int nr = idx >> 5, kp = (idx & 31) * 2;
        const __half2 h = __floats2half2_rn(t[kp][nr], t[kp + 1][nr]);
        *(__half2*)(Wt + (size_t)(n0 + nr) * K + k0 + kp) = h;
    }
}

__global__ void wtrans_all(const float* __restrict__ Wq,
                           const float* __restrict__ Wk,
                           const float* __restrict__ Wv,
                           const float* __restrict__ Wo,
                           const float* __restrict__ W1,
                           const float* __restrict__ W2,
                           __half* __restrict__ wqkv, __half* __restrict__ wo,
                           __half* __restrict__ w1,   __half* __restrict__ w2)
{
    const int t = blockIdx.x;
    if (t < 432) {
        const int z = t / 144, r = t % 144;
        const float* W = (z == 0) ? Wq : (z == 1) ? Wk : Wv;
        wtrans_tile(W, wqkv + (size_t)z * CDIM * CDIM, CDIM, CDIM,
                    (r % 12) * 64, (r / 12) * 64);
    } else if (t < 576) {
        const int r = t - 432;
        wtrans_tile(Wo, wo, CDIM, CDIM, (r % 12) * 64, (r / 12) * 64);
    } else if (t < 1152) {
        const int r = t - 576;
        wtrans_tile(W1, w1, CDIM, FDIM, (r % 48) * 64, (r / 48) * 64);
    } else {
        const int r = t - 1152;
        wtrans_tile(W2, w2, FDIM, CDIM, (r % 12) * 64, (r / 12) * 64);
    }
}
#define WTRANS_BLOCKS 1728

// ===========================================================================
// LayerNorm -> fp16 (one block per row, 192 threads)
// ===========================================================================
__global__ void ln_half(const float* __restrict__ x, const float* __restrict__ g,
                        const float* __restrict__ b, __half* __restrict__ out)
{
    const int row = blockIdx.x;
    const int t   = threadIdx.x;
    const float4 v = ((const float4*)(x + (size_t)row * CDIM))[t];

    float s = v.x + v.y + v.z + v.w;
    float q = v.x * v.x + v.y * v.y + v.z * v.z + v.w * v.w;
    __shared__ float ss[6], sq[6];
    #pragma unroll
    for (int off = 16; off > 0; off >>= 1) {
        s += __shfl_xor_sync(0xffffffffu, s, off);
        q += __shfl_xor_sync(0xffffffffu, q, off);
    }
    if ((t & 31) == 0) { ss[t >> 5] = s; sq[t >> 5] = q; }
    __syncthreads();
    s = ss[0] + ss[1] + ss[2] + ss[3] + ss[4] + ss[5];
    q = sq[0] + sq[1] + sq[2] + sq[3] + sq[4] + sq[5];

    const float mean = s * (1.0f / CDIM);
    const float var  = q * (1.0f / CDIM) - mean * mean;
    const float rstd = rsqrtf(var + 1e-5f);

    const float4 gv = ((const float4*)g)[t];
    const float4 bv = ((const float4*)b)[t];
    __half2 o01 = __floats2half2_rn((v.x - mean) * rstd * gv.x + bv.x,
                                    (v.y - mean) * rstd * gv.y + bv.y);
    __half2 o23 = __floats2half2_rn((v.z - mean) * rstd * gv.z + bv.z,
                                    (v.w - mean) * rstd * gv.w + bv.w);
    ((__half2*)(out + (size_t)row * CDIM))[t * 2]     = o01;
    ((__half2*)(out + (size_t)row * CDIM))[t * 2 + 1] = o23;
}

// ===========================================================================
// fp16 mma.sync GEMM (R10 config):  C[M,N] = A[M,K] @ B[N,K]^T
// EPI_HALF additionally scales columns < CDIM by QSCALE (Q pre-scale).
// ===========================================================================
enum { EPI_HALF = 0, EPI_BIAS_RES = 1, EPI_BIAS_GELU_H = 2 };

#define BM 128
#define BN 128
#define BK 64
#define ATILE (BM * BK * 2)
#define STAGE (ATILE * 2)
#define GEMM_SMEM (2 * STAGE)

__device__ __forceinline__ float gelu_exact(float x) {
    return 0.5f * x * (1.0f + erff(x * 0.7071067811865475f));
}

template <int EPI>
__global__ void __launch_bounds__(256)
gemm_mma(int M, int N, int K,
         const __half* __restrict__ A, const __half* __restrict__ B,
         const float* __restrict__ bias, const float* __restrict__ res,
         float* __restrict__ Cf, __half* __restrict__ Ch)
{
    extern __shared__ char smem[];
    const uint32_t sbase = smem_u32(smem);
    const int tid  = threadIdx.x;
    const int lane = tid & 31;
    const int wid  = tid >> 5;
    const int wm   = wid >> 1;
    const int wn   = wid & 1;
    const int brow = blockIdx.y * BM, bcol = blockIdx.x * BN;

    float acc[2][8][4];
    #pragma unroll
    for (int i = 0; i < 2; i++)
        #pragma unroll
        for (int j = 0; j < 8; j++)
            #pragma unroll
            for (int c = 0; c < 4; c++) acc[i][j][c] = 0.0f;

    const int nst = K / BK;
    const int lr0 = tid >> 3;
    const int lc  = (tid & 7) * 16;

    auto issue_stage = [&](int s) {
        const int k0  = s * BK;
        const uint32_t sA = sbase + (s & 1) * STAGE;
        const uint32_t sB = sA + ATILE;
        #pragma unroll
        for (int c = 0; c < 4; c++) {
            const int row = lr0 + c * 32;
            const uint32_t so = SWZ((uint32_t)(row * 128 + lc));
            CP_ASYNC16(sA + so, A + (size_t)(brow + row) * K + k0 + (lc >> 1));
            CP_ASYNC16(sB + so, B + (size_t)(bcol + row) * K + k0 + (lc >> 1));
        }
        CP_COMMIT();
    };

    issue_stage(0);
    issue_stage(1);

    const int a_row = wm * 32 + (lane & 15);
    const int a_kb  = (lane >> 4) << 4;
    const int b_row = wn * 64 + ((lane >> 4) << 3) + (lane & 7);
    const int b_kb  = ((lane >> 3) & 1) << 4;

    for (int s = 0; s < nst; s++) {
        if (s < nst - 1) CP_WAIT(1);
        else             CP_WAIT(0);
        __syncthreads();

        const uint32_t sA = sbase + (s & 1) * STAGE;
        const uint32_t sB = sA + ATILE;

        #pragma unroll
        for (int kk = 0; kk < 4; kk++) {
            uint32_t af[2][4], bf[4][4];
            #pragma unroll
            for (int mi = 0; mi < 2; mi++)
                ldsm4(af[mi], sA + SWZ((uint32_t)((a_row + mi * 16) * 128 +
                                                  a_kb + kk * 32)));
            #pragma unroll
            for (int bj = 0; bj < 4; bj++)
                ldsm4(bf[bj], sB + SWZ((uint32_t)((b_row + bj * 16) * 128 +
                                                  b_kb + kk * 32)));
            #pragma unroll
            for (int mi = 0; mi < 2; mi++)
                #pragma unroll
                for (int ni = 0; ni < 8; ni++)
                    mma16816(acc[mi][ni], af[mi],
                             bf[ni >> 1][(ni & 1) * 2],
                             bf[ni >> 1][(ni & 1) * 2 + 1]);
        }
        __syncthreads();
        if (s + 2 < nst) issue_stage(s + 2);
    }

    const int er = brow + wm * 32 + (lane >> 2);
    const int ec = bcol + wn * 64 + (lane & 3) * 2;
    #pragma unroll
    for (int mi = 0; mi < 2; mi++) {
        #pragma unroll
        for (int half = 0; half < 2; half++) {
            const int r = er + mi * 16 + half * 8;
            #pragma unroll
            for (int ni = 0; ni < 8; ni++) {
                const int c = ec + ni * 8;
                float d0 = acc[mi][ni][half * 2];
                float d1 = acc[mi][ni][half * 2 + 1];
                if (EPI == EPI_HALF) {
                    // Q columns pre-scaled for exp2-domain softmax
                    if (c < CDIM) { d0 *= QSCALE; d1 *= QSCALE; }
                    *(__half2*)(Ch + (size_t)r * N + c) = __floats2half2_rn(d0, d1);
                } else if (EPI == EPI_BIAS_RES) {
                    const float2 rv = *(const float2*)(res + (size_t)r * N + c);
                    *(float2*)(Cf + (size_t)r * N + c) =
                        make_float2(d0 + bias[c] + rv.x, d1 + bias[c + 1] + rv.y);
                } else {
                    const float a = gelu_exact(d0 + bias[c]);
                    const float b = gelu_exact(d1 + bias[c + 1]);
                    *(__half2*)(Ch + (size_t)r * N + c) = __floats2half2_rn(a, b);
                }
            }
        }
    }
}

// ===========================================================================
// fp16 mma flash attention, balanced: each block handles q-tiles
// (pair, 15-pair) => uniform 17 KV-tile iterations per block.
// 128 threads, Q tile 64, KV tile 64, exp2-domain softmax (Q pre-scaled).
// ===========================================================================
__global__ void __launch_bounds__(128)
attn_mma(const __half* __restrict__ qkv, __half* __restrict__ O)
{
    __shared__ __align__(128) char qs_raw[8192];
    __shared__ __align__(128) char ks_raw[8192];
    __shared__ __align__(128) char vs_raw[8192];
    const uint32_t qs = smem_u32(qs_raw);
    const uint32_t ks = smem_u32(ks_raw);
    const uint32_t vs = smem_u32(vs_raw);

    const int pair = blockIdx.x;        // 0..7
    const int bh = blockIdx.y;          // 0..95
    const int b  = bh / NHEAD, h = bh % NHEAD;
    const int tid = threadIdx.x, lane = tid & 31, w = tid >> 5;
    const size_t rowbase = (size_t)b * TDIM;

    for (int hh = 0; hh < 2; hh++) {
        const int qt = hh ? (15 - pair) : pair;

        // load Q tile (safe: prior half's smem reads all completed before its
        // KV-loop barriers; epilogue touches no smem)
        #pragma unroll
        for (int c = 0; c < 4; c++) {
            const int id = tid + c * 128;
            const int r = id >> 3, col = id & 7;
            const __half* src =
                qkv + (rowbase + qt * 64 + r) * QKVW + h * 64 + col * 8;
            *(uint4*)(qs_raw + SWZ((uint32_t)(r * 128 + col * 16))) =
                *(const uint4*)src;
        }
        __syncthreads();

        uint32_t qf[4][4];
        #pragma unroll
        for (int kk = 0; kk < 4; kk++)
            ldsm4(qf[kk], qs + SWZ((uint32_t)((w * 16 + (lane & 15)) * 128 +
                                              ((lane >> 4) << 4) + kk * 32)));

        float oacc[8][4];
        #pragma unroll
        for (int i = 0; i < 8; i++)
            #pragma unroll
            for (int j = 0; j < 4; j++) oacc[i][j] = 0.0f;
        float m0 = -INFINITY, m1 = -INFINITY, l0 = 0.0f, l1 = 0.0f;

        const int r0 = qt * 64 + w * 16 + (lane >> 2);
        const int r1 = r0 + 8;

        for (int jt = 0; jt <= qt; jt++) {
            __syncthreads();
            #pragma unroll
            for (int c = 0; c < 4; c++) {
                const int id = tid + c * 128;
                const int r = id >> 3, col = id & 7;
                const size_t grow =
                    (rowbase + jt * 64 + r) * QKVW + h * 64 + col * 8;
                const uint32_t so = SWZ((uint32_t)(r * 128 + col * 16));
                *(uint4*)(ks_raw + so) = *(const uint4*)(qkv + grow + 768);
                *(uint4*)(vs_raw + so) = *(const uint4*)(qkv + grow + 1536);
            }
            __syncthreads();

            float sacc[8][4];
            #pragma unroll
            for (int i = 0; i < 8; i++)
                #pragma unroll
                for (int j = 0; j < 4; j++) sacc[i][j] = 0.0f;
            #pragma unroll
            for (int kk = 0; kk < 4; kk++) {
                uint32_t bf[4][4];
                #pragma unroll
                for (int bj = 0; bj < 4; bj++)
                    ldsm4(bf[bj], ks + SWZ((uint32_t)(
                        (((lane >> 4) << 3) + (lane & 7) + bj * 16) * 128 +
                        (((lane >> 3) & 1) << 4) + kk * 32)));
                #pragma unroll
                for (int ni = 0; ni < 8; ni++)
                    mma16816(sacc[ni], qf[kk],
                             bf[ni >> 1][(ni & 1) * 2],
                             bf[ni >> 1][(ni & 1) * 2 + 1]);
            }

            // causal mask (scores already in log2 domain via Q pre-scale)
            #pragma unroll
            for (int ni = 0; ni < 8; ni++) {
                const int c = jt * 64 + ni * 8 + (lane & 3) * 2;
                if (c     > r0) sacc[ni][0] = -1e30f;
                if (c + 1 > r0) sacc[ni][1] = -1e30f;
                if (c     > r1) sacc[ni][2] = -1e30f;
                if (c + 1 > r1) sacc[ni][3] = -1e30f;
            }

            float mx0 = -INFINITY, mx1 = -INFINITY;
            #pragma unroll
            for (int ni = 0; ni < 8; ni++) {
                mx0 = fmaxf(mx0, fmaxf(sacc[ni][0], sacc[ni][1]));
                mx1 = fmaxf(mx1, fmaxf(sacc[ni][2], sacc[ni][3]));
            }
            #pragma unroll
            for (int off = 1; off < 4; off <<= 1) {
                mx0 = fmaxf(mx0, __shfl_xor_sync(0xffffffffu, mx0, off));
                mx1 = fmaxf(mx1, __shfl_xor_sync(0xffffffffu, mx1, off));
            }
            const float m0n = fmaxf(m0, mx0), m1n = fmaxf(m1, mx1);
            const float a0 = ex2(m0 - m0n), a1 = ex2(m1 - m1n);
            m0 = m0n; m1 = m1n;

            float rs0 = 0.0f, rs1 = 0.0f;
            uint32_t pf[8][2];
            #pragma unroll
            for (int ni = 0; ni < 8; ni++) {
                const float p0 = ex2(sacc[ni][0] - m0n);
                const float p1 = ex2(sacc[ni][1] - m0n);
                const float p2 = ex2(sacc[ni][2] - m1n);
                const float p3 = ex2(sacc[ni][3] - m1n);
                rs0 += p0 + p1; rs1 += p2 + p3;
                pf[ni][0] = pack_h2(p0, p1);
                pf[ni][1] = pack_h2(p2, p3);
            }
            #pragma unroll
            for (int off = 1; off < 4; off <<= 1) {
                rs0 += __shfl_xor_sync(0xffffffffu, rs0, off);
                rs1 += __shfl_xor_sync(0xffffffffu, rs1, off);
            }
            l0 = l0 * a0 + rs0;
            l1 = l1 * a1 + rs1;
            #pragma unroll
            for (int ni = 0; ni < 8; ni++) {
                oacc[ni][0] *= a0; oacc[ni][1] *= a0;
                oacc[ni][2] *= a1; oacc[ni][3] *= a1;
            }

            #pragma unroll
            for (int kk = 0; kk < 4; kk++) {
                uint32_t a[4] = { pf[2 * kk][0], pf[2 * kk][1],
                                  pf[2 * kk + 1][0], pf[2 * kk + 1][1] };
                #pragma unroll
                for (int vb = 0; vb < 4; vb++) {
                    uint32_t bv[4];
                    ldsm4t(bv, vs + SWZ((uint32_t)(
                        (kk * 16 + ((lane >> 3) & 1) * 8 + (lane & 7)) * 128 +
                        ((lane >> 4) & 1) * 16 + vb * 32)));
                    mma16816(oacc[vb * 2],     a, bv[0], bv[1]);
                    mma16816(oacc[vb * 2 + 1], a, bv[2], bv[3]);
                }
            }
        }

        const float il0 = 1.0f / l0, il1 = 1.0f / l1;
        const int orow = qt * 64 + w * 16 + (lane >> 2);
        #pragma unroll
        for (int ni = 0; ni < 8; ni++) {
            const int col = h * 64 + ni * 8 + (lane & 3) * 2;
            *(__half2*)(O + (rowbase + orow) * CDIM + col) =
                __floats2half2_rn(oacc[ni][0] * il0, oacc[ni][1] * il0);
            *(__half2*)(O + (rowbase + orow + 8) * CDIM + col) =
                __floats2half2_rn(oacc[ni][2] * il1, oacc[ni][3] * il1);
        }
    }
}

// ===========================================================================
// Launch  (our launch index 3 = attention => profiled by ncu)
// ===========================================================================
extern "C" void kernel_launch(void* const* d_in, const int* in_sizes, int n_in,
                              void* d_out, int out_size)
{
    const float* x   = (const float*)d_in[0];
    const float* Wq  = (const float*)d_in[1];
    const float* Wk  = (const float*)d_in[2];
    const float* Wv  = (const float*)d_in[3];
    const float* Wo  = (const float*)d_in[4];
    const float* bo  = (const float*)d_in[5];
    const float* W1  = (const float*)d_in[6];
    const float* b1  = (const float*)d_in[7];
    const float* W2  = (const float*)d_in[8];
    const float* b2  = (const float*)d_in[9];
    const float* g1  = (const float*)d_in[10];
    const float* be1 = (const float*)d_in[11];
    const float* g2  = (const float*)d_in[12];
    const float* be2 = (const float*)d_in[13];
    float* out = (float*)d_out;

    __half *h, *qkv, *att, *h2, *ff, *wqkv, *wo, *w1, *w2;
    float *x2;
    cudaGetSymbolAddress((void**)&h,    g_h);
    cudaGetSymbolAddress((void**)&qkv,  g_qkv);
    cudaGetSymbolAddress((void**)&att,  g_att);
    cudaGetSymbolAddress((void**)&h2,   g_h2);
    cudaGetSymbolAddress((void**)&ff,   g_ff);
    cudaGetSymbolAddress((void**)&wqkv, g_Wqkv);
    cudaGetSymbolAddress((void**)&wo,   g_Wo);
    cudaGetSymbolAddress((void**)&w1,   g_W1);
    cudaGetSymbolAddress((void**)&w2,   g_W2);
    cudaGetSymbolAddress((void**)&x2,   g_x2);

    cudaFuncSetAttribute((const void*)gemm_mma<EPI_HALF>,
                         cudaFuncAttributeMaxDynamicSharedMemorySize, GEMM_SMEM);
    cudaFuncSetAttribute((const void*)gemm_mma<EPI_BIAS_RES>,
                         cudaFuncAttributeMaxDynamicSharedMemorySize, GEMM_SMEM);
    cudaFuncSetAttribute((const void*)gemm_mma<EPI_BIAS_GELU_H>,
                         cudaFuncAttributeMaxDynamicSharedMemorySize, GEMM_SMEM);

    // 0: ALL weight transposes in one launch
    wtrans_all<<<WTRANS_BLOCKS, 256>>>(Wq, Wk, Wv, Wo, W1, W2, wqkv, wo, w1, w2);
    // 1: LN1
    ln_half<<<MROWS, 192>>>(x, g1, be1, h);
    // 2: fused QKV GEMM (Q pre-scaled in epilogue)
    gemm_mma<EPI_HALF><<<dim3(QKVW / BN, MROWS / BM), 256, GEMM_SMEM>>>(
        MROWS, QKVW, CDIM, h, wqkv, nullptr, nullptr, nullptr, qkv);
    // 3: attention (balanced pairs)  <- profiled by ncu
    attn_mma<<<dim3(8, BDIM * NHEAD), 128>>>(qkv, att);
    // 4: x2 = x + att @ Wo + bo
    gemm_mma<EPI_BIAS_RES><<<dim3(CDIM / BN, MROWS / BM), 256, GEMM_SMEM>>>(
        MROWS, CDIM, CDIM, att, wo, bo, x, x2, nullptr);
    // 5: LN2
    ln_half<<<MROWS, 192>>>(x2, g2, be2, h2);
    // 6: ff = gelu(h2 @ W1 + b1)
    gemm_mma<EPI_BIAS_GELU_H><<<dim3(FDIM / BN, MROWS / BM), 256, GEMM_SMEM>>>(
        MROWS, FDIM, CDIM, h2, w1, b1, nullptr, nullptr, ff);
    // 7: out = x2 + ff @ W2 + b2
    gemm_mma<EPI_BIAS_RES><<<dim3(CDIM / BN, MROWS / BM), 256, GEMM_SMEM>>>(
        MROWS, CDIM, FDIM, ff, w2, b2, x2, out, nullptr);
}

// round 17
// speedup vs baseline: 1.0598x; 1.0213x over previous
#include <cuda_runtime.h>
#include <cuda_fp16.h>
#include <math.h>
#include <stdint.h>

#define CDIM  768
#define TDIM  1024
#define BDIM  8
#define MROWS 8192
#define FDIM  3072
#define NHEAD 12
#define HSIZE 64
#define QKVW  2304
// 768^-0.5 * log2(e): Q pre-scale so softmax runs in exp2 domain
#define QSCALE 0.05205877179033723f

// ===========================================================================
// Scratch (no cudaMalloc allowed)
// ===========================================================================
__device__ __half g_h   [MROWS * CDIM];
__device__ __half g_qkv [MROWS * QKVW];
__device__ __half g_att [MROWS * CDIM];
__device__ __half g_h2  [MROWS * CDIM];
__device__ __half g_ff  [MROWS * FDIM];
__device__ float  g_x2  [MROWS * CDIM];
__device__ __half g_Wqkv[QKVW * CDIM];
__device__ __half g_Wo  [CDIM * CDIM];
__device__ __half g_W1  [CDIM * FDIM];
__device__ __half g_W2  [FDIM * CDIM];

__device__ __forceinline__ uint32_t smem_u32(const void* p) {
    uint32_t a;
    asm("{ .reg .u64 t; cvta.to.shared.u64 t, %1; cvt.u32.u64 %0, t; }"
        : "=r"(a) : "l"(p));
    return a;
}
#define SWZ(off) ((off) ^ (((off) >> 3) & 0x70))

__device__ __forceinline__ void ldsm4(uint32_t* r, uint32_t addr) {
    asm volatile("ldmatrix.sync.aligned.m8n8.x4.shared.b16 {%0,%1,%2,%3}, [%4];"
                 : "=r"(r[0]), "=r"(r[1]), "=r"(r[2]), "=r"(r[3]) : "r"(addr));
}
__device__ __forceinline__ void ldsm4t(uint32_t* r, uint32_t addr) {
    asm volatile("ldmatrix.sync.aligned.m8n8.x4.trans.shared.b16 {%0,%1,%2,%3}, [%4];"
                 : "=r"(r[0]), "=r"(r[1]), "=r"(r[2]), "=r"(r[3]) : "r"(addr));
}
__device__ __forceinline__ void mma16816(float* d, const uint32_t* a,
                                         uint32_t b0, uint32_t b1) {
    asm volatile("mma.sync.aligned.m16n8k16.row.col.f32.f16.f16.f32 "
                 "{%0,%1,%2,%3}, {%4,%5,%6,%7}, {%8,%9}, {%0,%1,%2,%3};"
                 : "+f"(d[0]), "+f"(d[1]), "+f"(d[2]), "+f"(d[3])
                 : "r"(a[0]), "r"(a[1]), "r"(a[2]), "r"(a[3]), "r"(b0), "r"(b1));
}
__device__ __forceinline__ uint32_t pack_h2(float a, float b) {
    __half2 h = __floats2half2_rn(a, b);
    return *(uint32_t*)&h;
}
__device__ __forceinline__ float ex2(float x) {
    float r;
    asm("ex2.approx.f32 %0, %1;" : "=f"(r) : "f"(x));
    return r;
}
#define CP_ASYNC16(dst, src) \
    asm volatile("cp.async.cg.shared.global [%0], [%1], 16;" :: "r"(dst), "l"(src))
#define CP_COMMIT() asm volatile("cp.async.commit_group;" ::: "memory")
#define CP_WAIT(n)  asm volatile("cp.async.wait_group %0;" :: "n"(n) : "memory")

// ===========================================================================
// Fused weight transpose:  all W[K,N] fp32 -> Wt[N,K] fp16 in ONE launch.
// ===========================================================================
__device__ __forceinline__ void wtrans_tile(const float* __restrict__ W,
                                            __half* __restrict__ Wt,
                                            int K, int N, int n0, int k0)
{
    __shared__ float t[64][65];
    const int tid = threadIdx.x;
    #pragma unroll
    for (int i = 0; i < 4; i++) {
        const int idx = tid + i * 256;
        const int kr = idx >> 4, nc = (idx & 15) * 4;
        const float4 v = *(const float4*)(W + (size_t)(k0 + kr) * N + n0 + nc);
        t[kr][nc] = v.x; t[kr][nc + 1] = v.y; t[kr][nc + 2] = v.z; t[kr][nc + 3] = v.w;
    }
    __syncthreads();
    #pragma unroll
    for (int i = 0; i < 8; i++) {
        const int idx = tid + i * 256;
        const int nr = idx >> 5, kp = (idx & 31) * 2;
        const __half2 h = __floats2half2_rn(t[kp][nr], t[kp + 1][nr]);
        *(__half2*)(Wt + (size_t)(n0 + nr) * K + k0 + kp) = h;
    }
}

__global__ void wtrans_all(const float* __restrict__ Wq,
                           const float* __restrict__ Wk,
                           const float* __restrict__ Wv,
                           const float* __restrict__ Wo,
                           const float* __restrict__ W1,
                           const float* __restrict__ W2,
                           __half* __restrict__ wqkv, __half* __restrict__ wo,
                           __half* __restrict__ w1,   __half* __restrict__ w2)
{
    const int t = blockIdx.x;
    if (t < 432) {
        const int z = t / 144, r = t % 144;
        const float* W = (z == 0) ? Wq : (z == 1) ? Wk : Wv;
        wtrans_tile(W, wqkv + (size_t)z * CDIM * CDIM, CDIM, CDIM,
                    (r % 12) * 64, (r / 12) * 64);
    } else if (t < 576) {
        const int r = t - 432;
        wtrans_tile(Wo, wo, CDIM, CDIM, (r % 12) * 64, (r / 12) * 64);
    } else if (t < 1152) {
        const int r = t - 576;
        wtrans_tile(W1, w1, CDIM, FDIM, (r % 48) * 64, (r / 48) * 64);
    } else {
        const int r = t - 1152;
        wtrans_tile(W2, w2, FDIM, CDIM, (r % 12) * 64, (r / 12) * 64);
    }
}
#define WTRANS_BLOCKS 1728

// ===========================================================================
// LayerNorm -> fp16 (one block per row, 192 threads)
// ===========================================================================
__global__ void ln_half(const float* __restrict__ x, const float* __restrict__ g,
                        const float* __restrict__ b, __half* __restrict__ out)
{
    const int row = blockIdx.x;
    const int t   = threadIdx.x;
    const float4 v = ((const float4*)(x + (size_t)row * CDIM))[t];

    float s = v.x + v.y + v.z + v.w;
    float q = v.x * v.x + v.y * v.y + v.z * v.z + v.w * v.w;
    __shared__ float ss[6], sq[6];
    #pragma unroll
    for (int off = 16; off > 0; off >>= 1) {
        s += __shfl_xor_sync(0xffffffffu, s, off);
        q += __shfl_xor_sync(0xffffffffu, q, off);
    }
    if ((t & 31) == 0) { ss[t >> 5] = s; sq[t >> 5] = q; }
    __syncthreads();
    s = ss[0] + ss[1] + ss[2] + ss[3] + ss[4] + ss[5];
    q = sq[0] + sq[1] + sq[2] + sq[3] + sq[4] + sq[5];

    const float mean = s * (1.0f / CDIM);
    const float var  = q * (1.0f / CDIM) - mean * mean;
    const float rstd = rsqrtf(var + 1e-5f);

    const float4 gv = ((const float4*)g)[t];
    const float4 bv = ((const float4*)b)[t];
    __half2 o01 = __floats2half2_rn((v.x - mean) * rstd * gv.x + bv.x,
                                    (v.y - mean) * rstd * gv.y + bv.y);
    __half2 o23 = __floats2half2_rn((v.z - mean) * rstd * gv.z + bv.z,
                                    (v.w - mean) * rstd * gv.w + bv.w);
    ((__half2*)(out + (size_t)row * CDIM))[t * 2]     = o01;
    ((__half2*)(out + (size_t)row * CDIM))[t * 2 + 1] = o23;
}

// ===========================================================================
// fp16 mma.sync GEMM (R10 config):  C[M,N] = A[M,K] @ B[N,K]^T
// EPI_HALF additionally scales columns < CDIM by QSCALE (Q pre-scale).
// ===========================================================================
enum { EPI_HALF = 0, EPI_BIAS_RES = 1, EPI_BIAS_GELU_H = 2 };

#define BM 128
#define BN 128
#define BK 64
#define ATILE (BM * BK * 2)
#define STAGE (ATILE * 2)
#define GEMM_SMEM (2 * STAGE)

__device__ __forceinline__ float gelu_exact(float x) {
    return 0.5f * x * (1.0f + erff(x * 0.7071067811865475f));
}

template <int EPI>
__global__ void __launch_bounds__(256)
gemm_mma(int M, int N, int K,
         const __half* __restrict__ A, const __half* __restrict__ B,
         const float* __restrict__ bias, const float* __restrict__ res,
         float* __restrict__ Cf, __half* __restrict__ Ch)
{
    extern __shared__ char smem[];
    const uint32_t sbase = smem_u32(smem);
    const int tid  = threadIdx.x;
    const int lane = tid & 31;
    const int wid  = tid >> 5;
    const int wm   = wid >> 1;
    const int wn   = wid & 1;
    const int brow = blockIdx.y * BM, bcol = blockIdx.x * BN;

    float acc[2][8][4];
    #pragma unroll
    for (int i = 0; i < 2; i++)
        #pragma unroll
        for (int j = 0; j < 8; j++)
            #pragma unroll
            for (int c = 0; c < 4; c++) acc[i][j][c] = 0.0f;

    const int nst = K / BK;
    const int lr0 = tid >> 3;
    const int lc  = (tid & 7) * 16;

    auto issue_stage = [&](int s) {
        const int k0  = s * BK;
        const uint32_t sA = sbase + (s & 1) * STAGE;
        const uint32_t sB = sA + ATILE;
        #pragma unroll
        for (int c = 0; c < 4; c++) {
            const int row = lr0 + c * 32;
            const uint32_t so = SWZ((uint32_t)(row * 128 + lc));
            CP_ASYNC16(sA + so, A + (size_t)(brow + row) * K + k0 + (lc >> 1));
            CP_ASYNC16(sB + so, B + (size_t)(bcol + row) * K + k0 + (lc >> 1));
        }
        CP_COMMIT();
    };

    issue_stage(0);
    issue_stage(1);

    const int a_row = wm * 32 + (lane & 15);
    const int a_kb  = (lane >> 4) << 4;
    const int b_row = wn * 64 + ((lane >> 4) << 3) + (lane & 7);
    const int b_kb  = ((lane >> 3) & 1) << 4;

    for (int s = 0; s < nst; s++) {
        if (s < nst - 1) CP_WAIT(1);
        else             CP_WAIT(0);
        __syncthreads();

        const uint32_t sA = sbase + (s & 1) * STAGE;
        const uint32_t sB = sA + ATILE;

        #pragma unroll
        for (int kk = 0; kk < 4; kk++) {
            uint32_t af[2][4], bf[4][4];
            #pragma unroll
            for (int mi = 0; mi < 2; mi++)
                ldsm4(af[mi], sA + SWZ((uint32_t)((a_row + mi * 16) * 128 +
                                                  a_kb + kk * 32)));
            #pragma unroll
            for (int bj = 0; bj < 4; bj++)
                ldsm4(bf[bj], sB + SWZ((uint32_t)((b_row + bj * 16) * 128 +
                                                  b_kb + kk * 32)));
            #pragma unroll
            for (int mi = 0; mi < 2; mi++)
                #pragma unroll
                for (int ni = 0; ni < 8; ni++)
                    mma16816(acc[mi][ni], af[mi],
                             bf[ni >> 1][(ni & 1) * 2],
                             bf[ni >> 1][(ni & 1) * 2 + 1]);
        }
        __syncthreads();
        if (s + 2 < nst) issue_stage(s + 2);
    }

    const int er = brow + wm * 32 + (lane >> 2);
    const int ec = bcol + wn * 64 + (lane & 3) * 2;
    #pragma unroll
    for (int mi = 0; mi < 2; mi++) {
        #pragma unroll
        for (int half = 0; half < 2; half++) {
            const int r = er + mi * 16 + half * 8;
            #pragma unroll
            for (int ni = 0; ni < 8; ni++) {
                const int c = ec + ni * 8;
                float d0 = acc[mi][ni][half * 2];
                float d1 = acc[mi][ni][half * 2 + 1];
                if (EPI == EPI_HALF) {
                    if (c < CDIM) { d0 *= QSCALE; d1 *= QSCALE; }
                    *(__half2*)(Ch + (size_t)r * N + c) = __floats2half2_rn(d0, d1);
                } else if (EPI == EPI_BIAS_RES) {
                    const float2 rv = *(const float2*)(res + (size_t)r * N + c);
                    *(float2*)(Cf + (size_t)r * N + c) =
                        make_float2(d0 + bias[c] + rv.x, d1 + bias[c + 1] + rv.y);
                } else {
                    const float a = gelu_exact(d0 + bias[c]);
                    const float b = gelu_exact(d1 + bias[c + 1]);
                    *(__half2*)(Ch + (size_t)r * N + c) = __floats2half2_rn(a, b);
                }
            }
        }
    }
}

// ===========================================================================
// fp16 mma flash attention, balanced pairs, cp.async KV staging,
// diagonal-only causal masking. 128 threads, Q/KV tiles 64.
// ===========================================================================
__global__ void __launch_bounds__(128)
attn_mma(const __half* __restrict__ qkv, __half* __restrict__ O)
{
    __shared__ __align__(128) char qs_raw[8192];
    __shared__ __align__(128) char ks_raw[8192];
    __shared__ __align__(128) char vs_raw[8192];
    const uint32_t qs = smem_u32(qs_raw);
    const uint32_t ks = smem_u32(ks_raw);
    const uint32_t vs = smem_u32(vs_raw);

    const int pair = blockIdx.x;        // 0..7
    const int bh = blockIdx.y;          // 0..95
    const int b  = bh / NHEAD, h = bh % NHEAD;
    const int tid = threadIdx.x, lane = tid & 31, w = tid >> 5;
    const size_t rowbase = (size_t)b * TDIM;

    for (int hh = 0; hh < 2; hh++) {
        const int qt = hh ? (15 - pair) : pair;

        // load Q tile via cp.async
        #pragma unroll
        for (int c = 0; c < 4; c++) {
            const int id = tid + c * 128;
            const int r = id >> 3, col = id & 7;
            CP_ASYNC16(qs + SWZ((uint32_t)(r * 128 + col * 16)),
                       qkv + (rowbase + qt * 64 + r) * QKVW + h * 64 + col * 8);
        }
        CP_COMMIT();
        CP_WAIT(0);
        __syncthreads();

        uint32_t qf[4][4];
        #pragma unroll
        for (int kk = 0; kk < 4; kk++)
            ldsm4(qf[kk], qs + SWZ((uint32_t)((w * 16 + (lane & 15)) * 128 +
                                              ((lane >> 4) << 4) + kk * 32)));

        float oacc[8][4];
        #pragma unroll
        for (int i = 0; i < 8; i++)
            #pragma unroll
            for (int j = 0; j < 4; j++) oacc[i][j] = 0.0f;
        float m0 = -INFINITY, m1 = -INFINITY, l0 = 0.0f, l1 = 0.0f;

        const int r0 = qt * 64 + w * 16 + (lane >> 2);
        const int r1 = r0 + 8;

        for (int jt = 0; jt <= qt; jt++) {
            __syncthreads();
            // KV staging via cp.async (no RF round trip)
            #pragma unroll
            for (int c = 0; c < 4; c++) {
                const int id = tid + c * 128;
                const int r = id >> 3, col = id & 7;
                const size_t grow =
                    (rowbase + jt * 64 + r) * QKVW + h * 64 + col * 8;
                const uint32_t so = SWZ((uint32_t)(r * 128 + col * 16));
                CP_ASYNC16(ks + so, qkv + grow + 768);
                CP_ASYNC16(vs + so, qkv + grow + 1536);
            }
            CP_COMMIT();
            CP_WAIT(0);
            __syncthreads();

            float sacc[8][4];
            #pragma unroll
            for (int i = 0; i < 8; i++)
                #pragma unroll
                for (int j = 0; j < 4; j++) sacc[i][j] = 0.0f;
            #pragma unroll
            for (int kk = 0; kk < 4; kk++) {
                uint32_t bf[4][4];
                #pragma unroll
                for (int bj = 0; bj < 4; bj++)
                    ldsm4(bf[bj], ks + SWZ((uint32_t)(
                        (((lane >> 4) << 3) + (lane & 7) + bj * 16) * 128 +
                        (((lane >> 3) & 1) << 4) + kk * 32)));
                #pragma unroll
                for (int ni = 0; ni < 8; ni++)
                    mma16816(sacc[ni], qf[kk],
                             bf[ni >> 1][(ni & 1) * 2],
                             bf[ni >> 1][(ni & 1) * 2 + 1]);
            }

            // causal mask needed only on the diagonal tile
            if (jt == qt) {
                #pragma unroll
                for (int ni = 0; ni < 8; ni++) {
                    const int c = jt * 64 + ni * 8 + (lane & 3) * 2;
                    if (c     > r0) sacc[ni][0] = -1e30f;
                    if (c + 1 > r0) sacc[ni][1] = -1e30f;
                    if (c     > r1) sacc[ni][2] = -1e30f;
                    if (c + 1 > r1) sacc[ni][3] = -1e30f;
                }
            }

            float mx0 = -INFINITY, mx1 = -INFINITY;
            #pragma unroll
            for (int ni = 0; ni < 8; ni++) {
                mx0 = fmaxf(mx0, fmaxf(sacc[ni][0], sacc[ni][1]));
                mx1 = fmaxf(mx1, fmaxf(sacc[ni][2], sacc[ni][3]));
            }
            #pragma unroll
            for (int off = 1; off < 4; off <<= 1) {
                mx0 = fmaxf(mx0, __shfl_xor_sync(0xffffffffu, mx0, off));
                mx1 = fmaxf(mx1, __shfl_xor_sync(0xffffffffu, mx1, off));
            }
            const float m0n = fmaxf(m0, mx0), m1n = fmaxf(m1, mx1);
            const float a0 = ex2(m0 - m0n), a1 = ex2(m1 - m1n);
            m0 = m0n; m1 = m1n;

            float rs0 = 0.0f, rs1 = 0.0f;
            uint32_t pf[8][2];
            #pragma unroll
            for (int ni = 0; ni < 8; ni++) {
                const float p0 = ex2(sacc[ni][0] - m0n);
                const float p1 = ex2(sacc[ni][1] - m0n);
                const float p2 = ex2(sacc[ni][2] - m1n);
                const float p3 = ex2(sacc[ni][3] - m1n);
                rs0 += p0 + p1; rs1 += p2 + p3;
                pf[ni][0] = pack_h2(p0, p1);
                pf[ni][1] = pack_h2(p2, p3);
            }
            #pragma unroll
            for (int off = 1; off < 4; off <<= 1) {
                rs0 += __shfl_xor_sync(0xffffffffu, rs0, off);
                rs1 += __shfl_xor_sync(0xffffffffu, rs1, off);
            }
            l0 = l0 * a0 + rs0;
            l1 = l1 * a1 + rs1;
            #pragma unroll
            for (int ni = 0; ni < 8; ni++) {
                oacc[ni][0] *= a0; oacc[ni][1] *= a0;
                oacc[ni][2] *= a1; oacc[ni][3] *= a1;
            }

            #pragma unroll
            for (int kk = 0; kk < 4; kk++) {
                uint32_t a[4] = { pf[2 * kk][0], pf[2 * kk][1],
                                  pf[2 * kk + 1][0], pf[2 * kk + 1][1] };
                #pragma unroll
                for (int vb = 0; vb < 4; vb++) {
                    uint32_t bv[4];
                    ldsm4t(bv, vs + SWZ((uint32_t)(
                        (kk * 16 + ((lane >> 3) & 1) * 8 + (lane & 7)) * 128 +
                        ((lane >> 4) & 1) * 16 + vb * 32)));
                    mma16816(oacc[vb * 2],     a, bv[0], bv[1]);
                    mma16816(oacc[vb * 2 + 1], a, bv[2], bv[3]);
                }
            }
        }

        const float il0 = 1.0f / l0, il1 = 1.0f / l1;
        const int orow = qt * 64 + w * 16 + (lane >> 2);
        #pragma unroll
        for (int ni = 0; ni < 8; ni++) {
            const int col = h * 64 + ni * 8 + (lane & 3) * 2;
            *(__half2*)(O + (rowbase + orow) * CDIM + col) =
                __floats2half2_rn(oacc[ni][0] * il0, oacc[ni][1] * il0);
            *(__half2*)(O + (rowbase + orow + 8) * CDIM + col) =
                __floats2half2_rn(oacc[ni][2] * il1, oacc[ni][3] * il1);
        }
    }
}

// ===========================================================================
// Launch  (our launch index 3 = attention => profiled by ncu)
// ===========================================================================
extern "C" void kernel_launch(void* const* d_in, const int* in_sizes, int n_in,
                              void* d_out, int out_size)
{
    const float* x   = (const float*)d_in[0];
    const float* Wq  = (const float*)d_in[1];
    const float* Wk  = (const float*)d_in[2];
    const float* Wv  = (const float*)d_in[3];
    const float* Wo  = (const float*)d_in[4];
    const float* bo  = (const float*)d_in[5];
    const float* W1  = (const float*)d_in[6];
    const float* b1  = (const float*)d_in[7];
    const float* W2  = (const float*)d_in[8];
    const float* b2  = (const float*)d_in[9];
    const float* g1  = (const float*)d_in[10];
    const float* be1 = (const float*)d_in[11];
    const float* g2  = (const float*)d_in[12];
    const float* be2 = (const float*)d_in[13];
    float* out = (float*)d_out;

    __half *h, *qkv, *att, *h2, *ff, *wqkv, *wo, *w1, *w2;
    float *x2;
    cudaGetSymbolAddress((void**)&h,    g_h);
    cudaGetSymbolAddress((void**)&qkv,  g_qkv);
    cudaGetSymbolAddress((void**)&att,  g_att);
    cudaGetSymbolAddress((void**)&h2,   g_h2);
    cudaGetSymbolAddress((void**)&ff,   g_ff);
    cudaGetSymbolAddress((void**)&wqkv, g_Wqkv);
    cudaGetSymbolAddress((void**)&wo,   g_Wo);
    cudaGetSymbolAddress((void**)&w1,   g_W1);
    cudaGetSymbolAddress((void**)&w2,   g_W2);
    cudaGetSymbolAddress((void**)&x2,   g_x2);

    cudaFuncSetAttribute((const void*)gemm_mma<EPI_HALF>,
                         cudaFuncAttributeMaxDynamicSharedMemorySize, GEMM_SMEM);
    cudaFuncSetAttribute((const void*)gemm_mma<EPI_BIAS_RES>,
                         cudaFuncAttributeMaxDynamicSharedMemorySize, GEMM_SMEM);
    cudaFuncSetAttribute((const void*)gemm_mma<EPI_BIAS_GELU_H>,
                         cudaFuncAttributeMaxDynamicSharedMemorySize, GEMM_SMEM);

    // 0: ALL weight transposes in one launch
    wtrans_all<<<WTRANS_BLOCKS, 256>>>(Wq, Wk, Wv, Wo, W1, W2, wqkv, wo, w1, w2);
    // 1: LN1
    ln_half<<<MROWS, 192>>>(x, g1, be1, h);
    // 2: fused QKV GEMM (Q pre-scaled in epilogue)
    gemm_mma<EPI_HALF><<<dim3(QKVW / BN, MROWS / BM), 256, GEMM_SMEM>>>(
        MROWS, QKVW, CDIM, h, wqkv, nullptr, nullptr, nullptr, qkv);
    // 3: attention (balanced pairs, cp.async staging)  <- profiled by ncu
    attn_mma<<<dim3(8, BDIM * NHEAD), 128>>>(qkv, att);
    // 4: x2 = x + att @ Wo + bo
    gemm_mma<EPI_BIAS_RES><<<dim3(CDIM / BN, MROWS / BM), 256, GEMM_SMEM>>>(
        MROWS, CDIM, CDIM, att, wo, bo, x, x2, nullptr);
    // 5: LN2
    ln_half<<<MROWS, 192>>>(x2, g2, be2, h2);
    // 6: ff = gelu(h2 @ W1 + b1)
    gemm_mma<EPI_BIAS_GELU_H><<<dim3(FDIM / BN, MROWS / BM), 256, GEMM_SMEM>>>(
        MROWS, FDIM, CDIM, h2, w1, b1, nullptr, nullptr, ff);
    // 7: out = x2 + ff @ W2 + b2
    gemm_mma<EPI_BIAS_RES><<<dim3(CDIM / BN, MROWS / BM), 256, GEMM_SMEM>>>(
        MROWS, CDIM, FDIM, ff, w2, b2, x2, out, nullptr);
}